// round 15
// baseline (speedup 1.0000x reference)
#include <cuda_runtime.h>
#include <cuda_fp16.h>
#include <cstdint>

// ---------------- problem constants ----------------
#define BATCH 4
#define NHEAD 8
#define NBH   32
#define DH    128
#define TT    2048
#define QT    128
#define KT    64
#define NITER (TT / KT)
#define SCALE_AL2E 7.21347520444482f

__device__ __half g_QT[(size_t)NBH * TT * DH];
__device__ __half g_KT[(size_t)NBH * TT * DH];
__device__ __half g_VB[(size_t)NBH * DH * TT];

#define OFF_LS   0
#define OFF_ST   512
#define KBYTES   17408
#define STAGE_BYTES 35840
#define NSTAGE   6
#define SMEM_BYTES (512 + NSTAGE * STAGE_BYTES)
#define LDKB 272
#define LDVB 144
#define LDO  130
#define ONESH2 0x3C003C00u

__device__ __forceinline__ uint32_t smem_u32(const void* p) {
    uint32_t a;
    asm("{ .reg .u64 t; cvta.to.shared.u64 t, %1; cvt.u32.u64 %0, t; }" : "=r"(a) : "l"(p));
    return a;
}
__device__ __forceinline__ void cp16(uint32_t d, const void* g) {
    uint64_t ga;
    asm("cvta.to.global.u64 %0, %1;" : "=l"(ga) : "l"(g));
    asm volatile("cp.async.cg.shared.global [%0], [%1], 16;" :: "r"(d), "l"(ga) : "memory");
}
#define CP_COMMIT() asm volatile("cp.async.commit_group;" ::: "memory")
#define CP_WAIT(n)  asm volatile("cp.async.wait_group %0;" :: "n"(n) : "memory")

__device__ __forceinline__ void ldsm4(uint32_t a, uint32_t* r) {
    asm volatile("ldmatrix.sync.aligned.m8n8.x4.shared.b16 {%0,%1,%2,%3}, [%4];"
        : "=r"(r[0]), "=r"(r[1]), "=r"(r[2]), "=r"(r[3]) : "r"(a));
}
__device__ __forceinline__ void mma16816(float* d, const uint32_t* a, uint32_t b0, uint32_t b1) {
    asm volatile("mma.sync.aligned.m16n8k16.row.col.f32.f16.f16.f32 "
        "{%0,%1,%2,%3}, {%4,%5,%6,%7}, {%8,%9}, {%0,%1,%2,%3};"
        : "+f"(d[0]), "+f"(d[1]), "+f"(d[2]), "+f"(d[3])
        : "r"(a[0]), "r"(a[1]), "r"(a[2]), "r"(a[3]), "r"(b0), "r"(b1));
}
__device__ __forceinline__ uint32_t ex2_f16x2(float lo, float hi) {
    __half2 h = __floats2half2_rn(lo, hi);
    uint32_t x = *reinterpret_cast<uint32_t*>(&h), r;
    asm("ex2.approx.f16x2 %0, %1;" : "=r"(r) : "r"(x));
    return r;
}

__device__ __forceinline__ void cp_ktile(uint32_t dst, const __half* src) {
    const int tid = threadIdx.x;
    #pragma unroll
    for (int j = 0; j < 4; j++) {
        int c = tid + j * 256;
        int row = c >> 4, cc = c & 15;
        cp16(dst + row * LDKB + cc * 16, src + row * DH + cc * 8);
    }
}
__device__ __forceinline__ void cp_vtile(uint32_t dst, const __half* src) {
    const int tid = threadIdx.x;
    #pragma unroll
    for (int j = 0; j < 4; j++) {
        int c = tid + j * 256;
        int row = c >> 3, cc = c & 7;
        cp16(dst + row * LDVB + cc * 16, src + (size_t)row * TT + cc * 8);
    }
}

// ---------------- prep (R13 verified) ----------------
__global__ __launch_bounds__(256) void prep_kernel(const float* __restrict__ q,
                                                   const float* __restrict__ k,
                                                   const float* __restrict__ v) {
    __shared__ float part[256];
    __shared__ __align__(16) __half outS[64 * 136];
    const int tid = threadIdx.x;
    const int z = blockIdx.z;

    if (z == 2) {
        const float4* v4 = reinterpret_cast<const float4*>(v);
        uint2* d2 = reinterpret_cast<uint2*>(g_VB);
        const size_t base = ((size_t)(blockIdx.y * gridDim.x + blockIdx.x)) * 2048 + tid;
        #pragma unroll
        for (int j = 0; j < 8; j++) {
            size_t e = base + (size_t)j * 256;
            float4 d = v4[e];
            __half2 h0 = __floats2half2_rn(d.x, d.y);
            __half2 h1 = __floats2half2_rn(d.z, d.w);
            d2[e] = make_uint2(*reinterpret_cast<uint32_t*>(&h0),
                               *reinterpret_cast<uint32_t*>(&h1));
        }
        return;
    }

    const int t = tid & 63, g = tid >> 6;
    const int t0 = blockIdx.x * 64, bh = blockIdx.y;
    const float* src = (z == 0 ? q : k) + (size_t)bh * DH * TT + t0 + t;
    float vals[32];
    #pragma unroll
    for (int i = 0; i < 32; i++) vals[i] = src[(size_t)(g * 32 + i) * TT];

    float ss = 0.f;
    #pragma unroll
    for (int i = 0; i < 32; i++) ss += vals[i] * vals[i];
    part[tid] = ss;
    __syncthreads();
    if (tid < 64)
        part[tid] = 1.0f / fmaxf(sqrtf(part[tid] + part[tid + 64] + part[tid + 128] + part[tid + 192]), 1e-12f);
    __syncthreads();
    const float inv = part[t] * (z == 0 ? SCALE_AL2E : 1.0f);

    #pragma unroll
    for (int i = 0; i < 16; i++) {
        __half2 h = __floats2half2_rn(vals[2 * i] * inv, vals[2 * i + 1] * inv);
        *reinterpret_cast<__half2*>(&outS[t * 136 + g * 32 + 2 * i]) = h;
    }
    __syncthreads();

    uint4* dstg = reinterpret_cast<uint4*>(
        (z == 0 ? g_QT : g_KT) + ((size_t)bh * TT + t0) * DH);
    #pragma unroll
    for (int p = 0; p < 4; p++) {
        int item = tid + p * 256;
        int tt = item >> 4, ch = item & 15;
        dstg[tt * 16 + ch] = *reinterpret_cast<uint4*>(&outS[tt * 136 + ch * 8]);
    }
}

// ---------------- one KT=64 tile: V-frags hoisted across the conv seam ----------------
__device__ __forceinline__ void compute_tile(uint32_t ks, uint32_t vs,
                                             const uint32_t qA[8][4],
                                             float oacc[16][4], float lacc[4],
                                             uint32_t brow, uint32_t bcol) {
    float sacc[8][4];
    #pragma unroll
    for (int j = 0; j < 8; j++)
        sacc[j][0] = sacc[j][1] = sacc[j][2] = sacc[j][3] = 0.f;

    uint32_t bk[2][4][4];
    #pragma unroll
    for (int j = 0; j < 4; j++)
        ldsm4(ks + (j * 16 + brow) * LDKB + bcol * 2, bk[0][j]);
    #pragma unroll
    for (int c = 0; c < 8; c++) {
        const int cur = c & 1;
        if (c < 7) {
            #pragma unroll
            for (int j = 0; j < 4; j++)
                ldsm4(ks + (j * 16 + brow) * LDKB + ((c + 1) * 16 + bcol) * 2, bk[cur ^ 1][j]);
        }
        #pragma unroll
        for (int j = 0; j < 4; j++) {
            mma16816(sacc[j * 2],     qA[c], bk[cur][j][0], bk[cur][j][1]);
            mma16816(sacc[j * 2 + 1], qA[c], bk[cur][j][2], bk[cur][j][3]);
        }
    }

    // hoist V-frag blocks 0 and 1 across the conv seam (independent of S)
    uint32_t bv[2][4][4];
    #pragma unroll
    for (int j = 0; j < 4; j++)
        ldsm4(vs + (j * 16 + brow) * LDVB + bcol * 2, bv[0][j]);

    uint32_t p[4][4];
    #pragma unroll
    for (int kc = 0; kc < 4; kc++) {
        const float* s0 = sacc[2 * kc];
        const float* s1 = sacc[2 * kc + 1];
        p[kc][0] = ex2_f16x2(s0[0], s0[1]);
        p[kc][1] = ex2_f16x2(s0[2], s0[3]);
        p[kc][2] = ex2_f16x2(s1[0], s1[1]);
        p[kc][3] = ex2_f16x2(s1[2], s1[3]);
        if (kc == 0) {
            #pragma unroll
            for (int j = 0; j < 4; j++)
                ldsm4(vs + ((4 + j) * 16 + brow) * LDVB + bcol * 2, bv[1][j]);
        }
    }

    // PV: consume slot blk&1 (filled at blk-2 / preload), refill AFTER consumption
    #pragma unroll
    for (int blk = 0; blk < 8; blk++) {
        const int cur = blk & 1;
        const int kc = blk >> 1, jh = blk & 1;
        #pragma unroll
        for (int jj = 0; jj < 4; jj++) {
            const int j = jh * 4 + jj;
            mma16816(oacc[j * 2],     p[kc], bv[cur][jj][0], bv[cur][jj][1]);
            mma16816(oacc[j * 2 + 1], p[kc], bv[cur][jj][2], bv[cur][jj][3]);
        }
        if (jh == 1) mma16816(lacc, p[kc], ONESH2, ONESH2);
        if (blk < 6) {
            const int nkc = (blk + 2) >> 1, njh = (blk + 2) & 1;
            #pragma unroll
            for (int j = 0; j < 4; j++)
                ldsm4(vs + ((njh * 4 + j) * 16 + brow) * LDVB + (nkc * 16 + bcol) * 2,
                      bv[cur][j]);
        }
    }
}

// ---------------- main attention kernel ----------------
__global__ __launch_bounds__(256, 1) void attn_main(float* __restrict__ out) {
    extern __shared__ char smem[];
    const int tid = threadIdx.x;
    const int lane = tid & 31;
    const int wr = tid >> 5;
    const int q0 = blockIdx.x * QT;
    const int bh = blockIdx.y;
    const uint32_t sb = smem_u32(smem);

    const __half* gq = g_QT + ((size_t)bh * TT + q0) * DH;
    const __half* gk = g_KT + (size_t)bh * TT * DH;
    const __half* gv = g_VB + (size_t)bh * DH * TT;

    #pragma unroll
    for (int j = 0; j < 8; j++) {
        int c = tid + j * 256;
        int row = c >> 4, cc = c & 15;
        cp16(sb + OFF_ST + row * LDKB + cc * 16, gq + row * DH + cc * 8);
    }
    CP_COMMIT();
    CP_WAIT(0);
    __syncthreads();

    uint32_t qA[8][4];
    {
        const uint32_t arow = ((lane >> 3) & 1) * 8 + (lane & 7);
        const uint32_t acol = ((lane >> 4) & 1) * 8;
        const uint32_t qb = sb + OFF_ST + (wr * 16 + arow) * LDKB + acol * 2;
        #pragma unroll
        for (int c = 0; c < 8; c++) ldsm4(qb + c * 32, qA[c]);
    }
    __syncthreads();

    #pragma unroll
    for (int g2 = 0; g2 < 2; g2++) {
        #pragma unroll
        for (int s = 0; s < 2; s++) {
            const int t = g2 * 2 + s;
            cp_ktile(sb + OFF_ST + t * STAGE_BYTES, gk + (size_t)t * KT * DH);
            cp_vtile(sb + OFF_ST + t * STAGE_BYTES + KBYTES, gv + t * KT);
        }
        CP_COMMIT();
    }

    float oacc[16][4];
    #pragma unroll
    for (int j = 0; j < 16; j++)
        oacc[j][0] = oacc[j][1] = oacc[j][2] = oacc[j][3] = 0.f;
    float lacc[4] = {0.f, 0.f, 0.f, 0.f};

    const uint32_t brow = ((lane >> 4) & 1) * 8 + (lane & 7);
    const uint32_t bcol = ((lane >> 3) & 1) * 8;

    for (int ii = 0; ii < NITER; ii += 2) {
        if (ii < NITER - 2) { CP_WAIT(1); } else { CP_WAIT(0); }
        __syncthreads();

        if (ii + 4 < NITER) {
            #pragma unroll
            for (int s = 0; s < 2; s++) {
                const int t = ii + 4 + s;
                const uint32_t st = sb + OFF_ST + (t % NSTAGE) * STAGE_BYTES;
                cp_ktile(st, gk + (size_t)t * KT * DH);
                cp_vtile(st + KBYTES, gv + (size_t)t * KT);
            }
            CP_COMMIT();
        }

        const uint32_t s0 = sb + OFF_ST + (ii % NSTAGE) * STAGE_BYTES;
        compute_tile(s0, s0 + KBYTES, qA, oacc, lacc, brow, bcol);
        const uint32_t s1 = sb + OFF_ST + ((ii + 1) % NSTAGE) * STAGE_BYTES;
        compute_tile(s1, s1 + KBYTES, qA, oacc, lacc, brow, bcol);
    }

    __syncthreads();
    float* Osf = reinterpret_cast<float*>(smem + OFF_ST);
    float* lsf = reinterpret_cast<float*>(smem + OFF_LS);
    const int r2 = lane >> 2, tg = lane & 3;
    #pragma unroll
    for (int jj = 0; jj < 16; jj++) {
        float2 v01 = make_float2(oacc[jj][0], oacc[jj][1]);
        float2 v23 = make_float2(oacc[jj][2], oacc[jj][3]);
        *reinterpret_cast<float2*>(&Osf[(wr * 16 + r2) * LDO + jj * 8 + tg * 2]) = v01;
        *reinterpret_cast<float2*>(&Osf[(wr * 16 + r2 + 8) * LDO + jj * 8 + tg * 2]) = v23;
    }
    if (tg == 0) {
        lsf[wr * 16 + r2]     = lacc[0];
        lsf[wr * 16 + r2 + 8] = lacc[2];
    }
    __syncthreads();
    if (tid < QT) lsf[tid] = 1.0f / lsf[tid];
    __syncthreads();

    float* ob = out + (size_t)bh * DH * TT + q0;
    #pragma unroll
    for (int dvi = 0; dvi < 16; dvi++) {
        const int dv = wr * 16 + dvi;
        #pragma unroll
        for (int s = 0; s < 4; s++) {
            const int qq = lane + s * 32;
            ob[(size_t)dv * TT + qq] = Osf[qq * LDO + dv] * lsf[qq];
        }
    }
}

extern "C" void kernel_launch(void* const* d_in, const int* in_sizes, int n_in,
                              void* d_out, int out_size) {
    const float* q = (const float*)d_in[0];
    const float* k = (const float*)d_in[1];
    const float* v = (const float*)d_in[2];
    float* out = (float*)d_out;

    cudaFuncSetAttribute(attn_main, cudaFuncAttributeMaxDynamicSharedMemorySize, SMEM_BYTES);

    prep_kernel<<<dim3(TT / 64, NBH, 3), 256>>>(q, k, v);
    attn_main<<<dim3(TT / QT, NBH), 256, SMEM_BYTES>>>(out);
}

// round 16
// speedup vs baseline: 1.0069x; 1.0069x over previous
#include <cuda_runtime.h>
#include <cuda_fp16.h>
#include <cstdint>

// ---------------- problem constants ----------------
#define BATCH 4
#define NHEAD 8
#define NBH   32
#define DH    128
#define TT    2048
#define QT    128
#define KT    64
#define NITER (TT / KT)
#define SCALE_AL2E 7.21347520444482f   // ALPHA * log2(e), folded into Q

__device__ __half g_KT[(size_t)NBH * TT * DH];  // [bh][t][ch], normalized
__device__ __half g_VB[(size_t)NBH * DH * TT];  // [bh][dv][t]

#define OFF_LS   0
#define OFF_ST   512
#define KBYTES   17408
#define STAGE_BYTES 35840
#define NSTAGE   6
#define SMEM_BYTES (512 + NSTAGE * STAGE_BYTES)
#define LDKB 272
#define LDVB 144
#define LDO  130

__device__ __forceinline__ uint32_t smem_u32(const void* p) {
    uint32_t a;
    asm("{ .reg .u64 t; cvta.to.shared.u64 t, %1; cvt.u32.u64 %0, t; }" : "=r"(a) : "l"(p));
    return a;
}
__device__ __forceinline__ void cp16(uint32_t d, const void* g) {
    uint64_t ga;
    asm("cvta.to.global.u64 %0, %1;" : "=l"(ga) : "l"(g));
    asm volatile("cp.async.cg.shared.global [%0], [%1], 16;" :: "r"(d), "l"(ga) : "memory");
}
#define CP_COMMIT() asm volatile("cp.async.commit_group;" ::: "memory")
#define CP_WAIT(n)  asm volatile("cp.async.wait_group %0;" :: "n"(n) : "memory")

__device__ __forceinline__ void ldsm4(uint32_t a, uint32_t* r) {
    asm volatile("ldmatrix.sync.aligned.m8n8.x4.shared.b16 {%0,%1,%2,%3}, [%4];"
        : "=r"(r[0]), "=r"(r[1]), "=r"(r[2]), "=r"(r[3]) : "r"(a));
}
__device__ __forceinline__ void mma16816(float* d, const uint32_t* a, uint32_t b0, uint32_t b1) {
    asm volatile("mma.sync.aligned.m16n8k16.row.col.f32.f16.f16.f32 "
        "{%0,%1,%2,%3}, {%4,%5,%6,%7}, {%8,%9}, {%0,%1,%2,%3};"
        : "+f"(d[0]), "+f"(d[1]), "+f"(d[2]), "+f"(d[3])
        : "r"(a[0]), "r"(a[1]), "r"(a[2]), "r"(a[3]), "r"(b0), "r"(b1));
}
__device__ __forceinline__ uint32_t ex2_f16x2(float lo, float hi) {
    __half2 h = __floats2half2_rn(lo, hi);
    uint32_t x = *reinterpret_cast<uint32_t*>(&h), r;
    asm("ex2.approx.f16x2 %0, %1;" : "=r"(r) : "r"(x));
    return r;
}

__device__ __forceinline__ void cp_ktile(uint32_t dst, const __half* src) {
    const int tid = threadIdx.x;
    #pragma unroll
    for (int j = 0; j < 4; j++) {
        int c = tid + j * 256;
        int row = c >> 4, cc = c & 15;
        cp16(dst + row * LDKB + cc * 16, src + row * DH + cc * 8);
    }
}
__device__ __forceinline__ void cp_vtile(uint32_t dst, const __half* src) {
    const int tid = threadIdx.x;
    #pragma unroll
    for (int j = 0; j < 4; j++) {
        int c = tid + j * 256;
        int row = c >> 3, cc = c & 7;
        cp16(dst + row * LDVB + cc * 16, src + (size_t)row * TT + cc * 8);
    }
}

// ---------------- prep: z=0 K-norm (coalesced, R13-verified path), z=1 V convert ----
__global__ __launch_bounds__(256) void prep_kernel(const float* __restrict__ k,
                                                   const float* __restrict__ v) {
    __shared__ float part[256];
    __shared__ __align__(16) __half outS[64 * 136];
    const int tid = threadIdx.x;
    const int z = blockIdx.z;

    if (z == 1) {   // flat V fp32->fp16
        const float4* v4 = reinterpret_cast<const float4*>(v);
        uint2* d2 = reinterpret_cast<uint2*>(g_VB);
        const size_t base = ((size_t)(blockIdx.y * gridDim.x + blockIdx.x)) * 2048 + tid;
        #pragma unroll
        for (int j = 0; j < 8; j++) {
            size_t e = base + (size_t)j * 256;
            float4 d = v4[e];
            __half2 h0 = __floats2half2_rn(d.x, d.y);
            __half2 h1 = __floats2half2_rn(d.z, d.w);
            d2[e] = make_uint2(*reinterpret_cast<uint32_t*>(&h0),
                               *reinterpret_cast<uint32_t*>(&h1));
        }
        return;
    }

    const int t = tid & 63, g = tid >> 6;
    const int t0 = blockIdx.x * 64, bh = blockIdx.y;
    const float* src = k + (size_t)bh * DH * TT + t0 + t;
    float vals[32];
    #pragma unroll
    for (int i = 0; i < 32; i++) vals[i] = src[(size_t)(g * 32 + i) * TT];

    float ss = 0.f;
    #pragma unroll
    for (int i = 0; i < 32; i++) ss += vals[i] * vals[i];
    part[tid] = ss;
    __syncthreads();
    if (tid < 64)
        part[tid] = 1.0f / fmaxf(sqrtf(part[tid] + part[tid + 64] + part[tid + 128] + part[tid + 192]), 1e-12f);
    __syncthreads();
    const float inv = part[t];

    #pragma unroll
    for (int i = 0; i < 16; i++) {
        __half2 h = __floats2half2_rn(vals[2 * i] * inv, vals[2 * i + 1] * inv);
        *reinterpret_cast<__half2*>(&outS[t * 136 + g * 32 + 2 * i]) = h;
    }
    __syncthreads();

    uint4* dstg = reinterpret_cast<uint4*>(g_KT + ((size_t)bh * TT + t0) * DH);
    #pragma unroll
    for (int p = 0; p < 4; p++) {
        int item = tid + p * 256;
        int tt = item >> 4, ch = item & 15;
        dstg[tt * 16 + ch] = *reinterpret_cast<uint4*>(&outS[tt * 136 + ch * 8]);
    }
}

// ---------------- one KT=64 tile (R10-verified gemms, shuffle rowsum) ----------------
__device__ __forceinline__ void compute_tile(uint32_t ks, uint32_t vs,
                                             const uint32_t qA[8][4],
                                             float oacc[16][4], float& l0, float& l1,
                                             uint32_t brow, uint32_t bcol) {
    float sacc[8][4];
    #pragma unroll
    for (int j = 0; j < 8; j++)
        sacc[j][0] = sacc[j][1] = sacc[j][2] = sacc[j][3] = 0.f;

    uint32_t bk[2][4][4];
    #pragma unroll
    for (int j = 0; j < 4; j++)
        ldsm4(ks + (j * 16 + brow) * LDKB + bcol * 2, bk[0][j]);
    #pragma unroll
    for (int c = 0; c < 8; c++) {
        const int cur = c & 1;
        if (c < 7) {
            #pragma unroll
            for (int j = 0; j < 4; j++)
                ldsm4(ks + (j * 16 + brow) * LDKB + ((c + 1) * 16 + bcol) * 2, bk[cur ^ 1][j]);
        }
        #pragma unroll
        for (int j = 0; j < 4; j++) {
            mma16816(sacc[j * 2],     qA[c], bk[cur][j][0], bk[cur][j][1]);
            mma16816(sacc[j * 2 + 1], qA[c], bk[cur][j][2], bk[cur][j][3]);
        }
    }

    uint32_t p[4][4];
    #pragma unroll
    for (int kc = 0; kc < 4; kc++) {
        const float* s0 = sacc[2 * kc];
        const float* s1 = sacc[2 * kc + 1];
        p[kc][0] = ex2_f16x2(s0[0], s0[1]);   // row r,   cols block 0
        p[kc][1] = ex2_f16x2(s0[2], s0[3]);   // row r+8, cols block 0
        p[kc][2] = ex2_f16x2(s1[0], s1[1]);   // row r,   cols block 1
        p[kc][3] = ex2_f16x2(s1[2], s1[3]);   // row r+8, cols block 1
    }

    // ---- O += P.V^T, pipelined V-frag loads ----
    uint32_t bv[2][4][4];
    #pragma unroll
    for (int j = 0; j < 4; j++)
        ldsm4(vs + (j * 16 + brow) * LDVB + bcol * 2, bv[0][j]);
    #pragma unroll
    for (int blk = 0; blk < 8; blk++) {
        const int cur = blk & 1;
        const int kc = blk >> 1, jh = blk & 1;
        if (blk < 7) {
            const int nkc = (blk + 1) >> 1, njh = (blk + 1) & 1;
            #pragma unroll
            for (int j = 0; j < 4; j++)
                ldsm4(vs + ((njh * 4 + j) * 16 + brow) * LDVB + (nkc * 16 + bcol) * 2,
                      bv[cur ^ 1][j]);
        }
        #pragma unroll
        for (int jj = 0; jj < 4; jj++) {
            const int j = jh * 4 + jj;
            mma16816(oacc[j * 2],     p[kc], bv[cur][jj][0], bv[cur][jj][1]);
            mma16816(oacc[j * 2 + 1], p[kc], bv[cur][jj][2], bv[cur][jj][3]);
        }
    }

    // ---- rowsum of P on fma/alu pipes (replaces 4 ones-HMMA) ----
    {
        const __half2* hp = reinterpret_cast<const __half2*>(&p[0][0]);  // hp[kc*4+j]
        // row r: regs j=0 and j=2 of each kc; row r+8: j=1 and j=3
        __half2 t0 = __hadd2(hp[0], hp[2]);
        t0 = __hadd2(t0, __hadd2(hp[4], hp[6]));
        t0 = __hadd2(t0, __hadd2(hp[8], hp[10]));
        t0 = __hadd2(t0, __hadd2(hp[12], hp[14]));
        __half2 t1 = __hadd2(hp[1], hp[3]);
        t1 = __hadd2(t1, __hadd2(hp[5], hp[7]));
        t1 = __hadd2(t1, __hadd2(hp[9], hp[11]));
        t1 = __hadd2(t1, __hadd2(hp[13], hp[15]));
        float f0 = __low2float(t0) + __high2float(t0);
        float f1 = __low2float(t1) + __high2float(t1);
        f0 += __shfl_xor_sync(0xffffffffu, f0, 1);
        f0 += __shfl_xor_sync(0xffffffffu, f0, 2);
        f1 += __shfl_xor_sync(0xffffffffu, f1, 1);
        f1 += __shfl_xor_sync(0xffffffffu, f1, 2);
        l0 += f0;
        l1 += f1;
    }
}

// ---------------- main attention kernel (fused Q-normalize prologue) ----------------
__global__ __launch_bounds__(256, 1) void attn_main(const float* __restrict__ qf,
                                                    float* __restrict__ out) {
    extern __shared__ char smem[];
    const int tid = threadIdx.x;
    const int lane = tid & 31;
    const int wr = tid >> 5;
    const int q0 = blockIdx.x * QT;
    const int bh = blockIdx.y;
    const uint32_t sb = smem_u32(smem);

    const __half* gk = g_KT + (size_t)bh * TT * DH;
    const __half* gv = g_VB + (size_t)bh * DH * TT;

    // ---- 1) launch K/V prefetch for tiles 0..3 FIRST (hides Q work in rampup) ----
    #pragma unroll
    for (int g2 = 0; g2 < 2; g2++) {
        #pragma unroll
        for (int s = 0; s < 2; s++) {
            const int t = g2 * 2 + s;
            cp_ktile(sb + OFF_ST + t * STAGE_BYTES, gk + (size_t)t * KT * DH);
            cp_vtile(sb + OFF_ST + t * STAGE_BYTES + KBYTES, gv + t * KT);
        }
        CP_COMMIT();
    }

    // ---- 2) fused Q normalize: raw fp32 [ch][t] -> fp16 [t][ch] in stage4 ----
    {
        const int t = tid & 127, g = tid >> 7;                 // 128 t x 2 ch-groups
        const float* qp = qf + (size_t)bh * DH * TT + q0 + t;  // + ch*TT
        float ss = 0.f;
        #pragma unroll
        for (int i = 0; i < 64; i++) {
            float x = qp[(size_t)(g * 64 + i) * TT];
            ss += x * x;
        }
        float* part = reinterpret_cast<float*>(smem + OFF_ST + 5 * STAGE_BYTES);
        part[tid] = ss;
        __syncthreads();
        if (tid < 128)
            part[256 + tid] = 1.0f / fmaxf(sqrtf(part[tid] + part[tid + 128]), 1e-12f);
        __syncthreads();
        const float sc = part[256 + t] * SCALE_AL2E;
        char* Qs = smem + OFF_ST + 4 * STAGE_BYTES;
        #pragma unroll
        for (int i = 0; i < 32; i++) {
            int ch = g * 64 + 2 * i;
            __half2 h = __floats2half2_rn(qp[(size_t)ch * TT] * sc,
                                          qp[(size_t)(ch + 1) * TT] * sc);
            *reinterpret_cast<__half2*>(Qs + t * LDKB + ch * 2) = h;
        }
    }
    __syncthreads();

    // ---- 3) extract persistent Q A-fragments from stage4 ----
    uint32_t qA[8][4];
    {
        const uint32_t arow = ((lane >> 3) & 1) * 8 + (lane & 7);
        const uint32_t acol = ((lane >> 4) & 1) * 8;
        const uint32_t qb = sb + OFF_ST + 4 * STAGE_BYTES + (wr * 16 + arow) * LDKB + acol * 2;
        #pragma unroll
        for (int c = 0; c < 8; c++) ldsm4(qb + c * 32, qA[c]);
    }
    __syncthreads();   // stage4/5 now free for the pipeline

    float oacc[16][4];
    #pragma unroll
    for (int j = 0; j < 16; j++)
        oacc[j][0] = oacc[j][1] = oacc[j][2] = oacc[j][3] = 0.f;
    float l0 = 0.f, l1 = 0.f;

    const uint32_t brow = ((lane >> 4) & 1) * 8 + (lane & 7);
    const uint32_t bcol = ((lane >> 3) & 1) * 8;

    for (int ii = 0; ii < NITER; ii += 2) {
        if (ii < NITER - 2) { CP_WAIT(1); } else { CP_WAIT(0); }
        __syncthreads();

        if (ii + 4 < NITER) {
            #pragma unroll
            for (int s = 0; s < 2; s++) {
                const int t = ii + 4 + s;
                const uint32_t st = sb + OFF_ST + (t % NSTAGE) * STAGE_BYTES;
                cp_ktile(st, gk + (size_t)t * KT * DH);
                cp_vtile(st + KBYTES, gv + (size_t)t * KT);
            }
            CP_COMMIT();
        }

        const uint32_t s0 = sb + OFF_ST + (ii % NSTAGE) * STAGE_BYTES;
        compute_tile(s0, s0 + KBYTES, qA, oacc, l0, l1, brow, bcol);
        const uint32_t s1 = sb + OFF_ST + ((ii + 1) % NSTAGE) * STAGE_BYTES;
        compute_tile(s1, s1 + KBYTES, qA, oacc, l0, l1, brow, bcol);
    }

    // ---- epilogue ----
    __syncthreads();
    float* Osf = reinterpret_cast<float*>(smem + OFF_ST);
    float* lsf = reinterpret_cast<float*>(smem + OFF_LS);
    const int r2 = lane >> 2, tg = lane & 3;
    #pragma unroll
    for (int jj = 0; jj < 16; jj++) {
        float2 v01 = make_float2(oacc[jj][0], oacc[jj][1]);
        float2 v23 = make_float2(oacc[jj][2], oacc[jj][3]);
        *reinterpret_cast<float2*>(&Osf[(wr * 16 + r2) * LDO + jj * 8 + tg * 2]) = v01;
        *reinterpret_cast<float2*>(&Osf[(wr * 16 + r2 + 8) * LDO + jj * 8 + tg * 2]) = v23;
    }
    if (tg == 0) {
        lsf[wr * 16 + r2]     = l0;
        lsf[wr * 16 + r2 + 8] = l1;
    }
    __syncthreads();
    if (tid < QT) lsf[tid] = 1.0f / lsf[tid];
    __syncthreads();

    float* ob = out + (size_t)bh * DH * TT + q0;
    #pragma unroll
    for (int dvi = 0; dvi < 16; dvi++) {
        const int dv = wr * 16 + dvi;
        #pragma unroll
        for (int s = 0; s < 4; s++) {
            const int qq = lane + s * 32;
            ob[(size_t)dv * TT + qq] = Osf[qq * LDO + dv] * lsf[qq];
        }
    }
}

extern "C" void kernel_launch(void* const* d_in, const int* in_sizes, int n_in,
                              void* d_out, int out_size) {
    const float* q = (const float*)d_in[0];
    const float* k = (const float*)d_in[1];
    const float* v = (const float*)d_in[2];
    float* out = (float*)d_out;

    cudaFuncSetAttribute(attn_main, cudaFuncAttributeMaxDynamicSharedMemorySize, SMEM_BYTES);

    prep_kernel<<<dim3(TT / 64, NBH, 2), 256>>>(k, v);
    attn_main<<<dim3(TT / QT, NBH), 256, SMEM_BYTES>>>(q, out);
}